// round 7
// baseline (speedup 1.0000x reference)
#include <cuda_runtime.h>

#define HW      256
#define NB      8
#define CH      64
#define HWHW    65536
#define NROWS   (NB * HW)                     // 2048 image rows
#define NUNITS  (NROWS * 2)                   // 4096 half-row units
#define GRID    148
#define THREADS 512
#define ITERS   ((NUNITS + GRID - 1) / GRID)  // 28

#define HB          128                        // pixels per half-row
#define XBUF_BYTES  (2 * CH * HB * 4)          // 64 KB per stage
#define XPART       (3 * XBUF_BYTES)           // 196608: norm partials
#define F1OFF       (XPART + 8192)             // 204800
#define F2OFF       (F1OFF + 512)              // 205312
#define SMEM_TOTAL  (F2OFF + 512)              // 205824 bytes

__device__ float g_n1[NROWS * HW];
__device__ float g_n2[NROWS * HW];
__device__ int   g_flag[NROWS];

extern __shared__ char smem[];

__global__ void k_reset() {
    g_flag[blockIdx.x * blockDim.x + threadIdx.x] = 0;
}

// Prefetch half-row unit u into smem stage. Each thread: 8x cp.async.cg 16B.
// ALWAYS commits a group (possibly empty) so group counting stays aligned.
__device__ __forceinline__ void prefetch_unit(const float* __restrict__ x1,
                                              const float* __restrict__ x2,
                                              int u, int stage, int tid) {
    if (u < NUNITS) {
        const int b = u >> 9, r = (u >> 1) & 255, h = u & 1;
        char* dst0 = smem + stage * XBUF_BYTES;
#pragma unroll
        for (int i = 0; i < 8; ++i) {
            const int l    = i * THREADS + tid;   // 0..4095, warp-coalesced
            const int arr  = l >> 11;
            const int ch   = (l >> 5) & 63;
            const int quad = l & 31;
            const float* src = (arr ? x2 : x1)
                + (size_t)(b * CH + ch) * HWHW + (size_t)r * HW + h * HB + quad * 4;
            unsigned saddr = (unsigned)__cvta_generic_to_shared(
                dst0 + ((arr * CH + ch) * HB + quad * 4) * 4);
            asm volatile("cp.async.cg.shared.global [%0], [%1], 16;"
                         :: "r"(saddr), "l"(src) : "memory");
        }
    }
    asm volatile("cp.async.commit_group;" ::: "memory");
}

__global__ void __launch_bounds__(THREADS, 1)
k_fused(const float* __restrict__ x1, const float* __restrict__ x2,
        const float* __restrict__ w,  const float* __restrict__ bias,
        float* __restrict__ out) {
    const int tid = threadIdx.x;
    const int bid = blockIdx.x;

    float wv[9];
#pragma unroll
    for (int i = 0; i < 9; i++) wv[i] = w[i];
    const float bv = bias[0];

    // pipeline prologue: 2 stages in flight
    prefetch_unit(x1, x2, bid,          0, tid);
    prefetch_unit(x1, x2, bid + GRID,   1, tid);

    for (int it = 0; it < ITERS; ++it) {
        // keep DRAM busy: issue stage it+2 before any waiting
        prefetch_unit(x1, x2, bid + (it + 2) * GRID, (it + 2) % 3, tid);
        asm volatile("cp.async.wait_group 2;" ::: "memory");
        __syncthreads();

        const int  u     = bid + it * GRID;
        const bool valid = (u < NUNITS);
        const int  b = u >> 9, r = (u >> 1) & 255, h = u & 1, gr = u >> 1;
        const float4* xb = (const float4*)(smem + (it % 3) * XBUF_BYTES);

        // ---- norm partials from smem: thread = (arr, ch-octet, quad) ----
        if (valid) {
            const int arr = tid >> 8, chh = (tid >> 5) & 7, quad = tid & 31;
            const float4* p = xb + (arr * CH + chh * 8) * (HB / 4) + quad;
            float4 s = make_float4(0.f, 0.f, 0.f, 0.f);
#pragma unroll
            for (int j = 0; j < 8; ++j) {
                const float4 a = p[j * (HB / 4)];
                s.x += fabsf(a.x); s.y += fabsf(a.y);
                s.z += fabsf(a.z); s.w += fabsf(a.w);
            }
            ((float4*)(smem + XPART))[(arr * 8 + chh) * 32 + quad] = s;
        }
        __syncthreads();

        // ---- reduce 8 octet-partials, write norm half-row, publish ----
        if (valid && tid < 64) {
            const int arr = tid >> 5, quad = tid & 31;
            const float4* p = (const float4*)(smem + XPART) + arr * 256 + quad;
            float4 s = p[0];
#pragma unroll
            for (int j = 1; j < 8; ++j) {
                const float4 a = p[j * 32];
                s.x += a.x; s.y += a.y; s.z += a.z; s.w += a.w;
            }
            float* dst = arr ? g_n2 : g_n1;
            ((float4*)(dst + (size_t)gr * HW + h * HB))[quad] = s;
            __threadfence();
        }
        __syncthreads();
        if (valid && tid == 0) {
            atomicAdd(&g_flag[gr], 1);
            // wait for both halves of rows gr-1, gr, gr+1 (same image)
            while (*(volatile int*)&g_flag[gr] < 2) {}
            if (r > 0)   while (*(volatile int*)&g_flag[gr - 1] < 2) {}
            if (r < 255) while (*(volatile int*)&g_flag[gr + 1] < 2) {}
            __threadfence();
        }
        __syncthreads();

        // ---- blend factors for the 128 pixels of this half-row ----
        if (valid && tid < HB) {
            const int col = h * HB + tid;
            float c1 = bv, c2 = bv;
#pragma unroll
            for (int di = 0; di < 3; ++di) {
                const int rr = r + di - 1;
                if (rr < 0 || rr >= HW) continue;
                const float* n1r = g_n1 + ((size_t)(b * HW + rr)) * HW;
                const float* n2r = g_n2 + ((size_t)(b * HW + rr)) * HW;
#pragma unroll
                for (int dj = 0; dj < 3; ++dj) {
                    const int cc = col + dj - 1;
                    if (cc < 0 || cc >= HW) continue;
                    const float ww = wv[di * 3 + dj];
                    c1 += ww * n1r[cc];
                    c2 += ww * n2r[cc];
                }
            }
            const float rd = 1.0f / (c1 + c2);
            ((float*)(smem + F1OFF))[tid] = c1 * rd;
            ((float*)(smem + F2OFF))[tid] = c2 * rd;
        }
        __syncthreads();

        // ---- blend from SMEM (no global re-read), streaming store ----
        if (valid) {
            const float4* f1v = (const float4*)(smem + F1OFF);
            const float4* f2v = (const float4*)(smem + F2OFF);
            float4* po = (float4*)(out + (size_t)b * CH * HWHW
                                       + (size_t)r * HW + h * HB);
#pragma unroll
            for (int i = 0; i < 4; ++i) {
                const int qi   = i * THREADS + tid;   // 0..2047
                const int ch   = qi >> 5;
                const int quad = qi & 31;
                const float4 a  = xb[ch * (HB / 4) + quad];             // x1
                const float4 v  = xb[(CH + ch) * (HB / 4) + quad];      // x2
                const float4 F1 = f1v[quad];
                const float4 F2 = f2v[quad];
                float4 o;
                o.x = a.x * F1.x + v.x * F2.x;
                o.y = a.y * F1.y + v.y * F2.y;
                o.z = a.z * F1.z + v.z * F2.z;
                o.w = a.w * F1.w + v.w * F2.w;
                __stcs(po + (size_t)ch * (HWHW / 4) + quad, o);
            }
        }
        __syncthreads();   // xbuf/f reuse guard before next prefetch overwrite
    }
}

extern "C" void kernel_launch(void* const* d_in, const int* in_sizes, int n_in,
                              void* d_out, int out_size) {
    const float* x1   = (const float*)d_in[0];
    const float* x2   = (const float*)d_in[1];
    const float* w    = (const float*)d_in[2];
    const float* bias = (const float*)d_in[3];
    float*       out  = (float*)d_out;

    cudaFuncSetAttribute(k_fused, cudaFuncAttributeMaxDynamicSharedMemorySize,
                         SMEM_TOTAL);

    k_reset<<<NROWS / 256, 256>>>();
    k_fused<<<GRID, THREADS, SMEM_TOTAL>>>(x1, x2, w, bias, out);
}